// round 3
// baseline (speedup 1.0000x reference)
#include <cuda_runtime.h>
#include <cstdint>

// CTC loss forward, warp-specialized producer/consumer per batch row.
// B=2048, T=256, C=128, L=32, S=65.
// Block = 4 warps per row: warps 0..2 produce normalized per-state probs
// p[ext[s]] into a shared ring; warp 3 runs the serial alpha recursion.
#define T_DIM 256
#define C_DIM 128
#define L_DIM 32
#define NPROD 3
#define RING  16   // ring slots (power of two)

__device__ __forceinline__ int ldacq(const int* p) {
    int v; unsigned a = (unsigned)__cvta_generic_to_shared(p);
    asm volatile("ld.acquire.cta.shared.b32 %0, [%1];" : "=r"(v) : "r"(a) : "memory");
    return v;
}
__device__ __forceinline__ void strel(int* p, int v) {
    unsigned a = (unsigned)__cvta_generic_to_shared(p);
    asm volatile("st.release.cta.shared.b32 [%0], %1;" :: "r"(a), "r"(v) : "memory");
}

__global__ __launch_bounds__(128)
void ctc_kernel(const int* __restrict__ y_true,
                const float* __restrict__ y_pred,
                float* __restrict__ out, int B)
{
    __shared__ float rec[RING][68];      // per-state probs: [s=0..64] per slot
    __shared__ float esc[NPROD][C_DIM];  // per-producer exp scratch
    __shared__ int   ready[RING];
    __shared__ int   cons_t;

    const int tid  = threadIdx.x;
    const int w    = tid >> 5;
    const int lane = tid & 31;
    const int b    = blockIdx.x;
    const unsigned FULL = 0xffffffffu;

    if (tid < RING) ready[tid] = -1;
    if (tid == 0)   cons_t = 0;
    __syncthreads();

    const int* lab = y_true + (size_t)b * L_DIM;
    // states owned per lane: s0 = lane, s1 = lane+32 (s=64 handled separately)
    int ext0 = 0, ext1 = 0;              // class index per state (0 = blank)
    if (lane & 1) { ext0 = lab[lane >> 1]; ext1 = lab[16 + (lane >> 1)]; }

    if (w < NPROD) {
        // ---------------- producer: timesteps t = w, w+NPROD, ... ----------
        const float4* rowp =
            reinterpret_cast<const float4*>(y_pred + (size_t)b * T_DIM * C_DIM);
        float4 x0 = rowp[(size_t)w * 32 + lane];
        float4 x1 = (w + NPROD < T_DIM) ? rowp[(size_t)(w + NPROD) * 32 + lane] : x0;

        for (int t = w; t < T_DIM; t += NPROD) {
            // backpressure: may write slot only if t < cons_t + RING
            while (t - ldacq(&cons_t) >= RING) { __nanosleep(40); }

            float4 x = x0; x0 = x1;
            if (t + 2 * NPROD < T_DIM)
                x1 = rowp[(size_t)(t + 2 * NPROD) * 32 + lane];

            float e0 = __expf(x.x), e1 = __expf(x.y);
            float e2 = __expf(x.z), e3 = __expf(x.w);
            reinterpret_cast<float4*>(esc[w])[lane] = make_float4(e0, e1, e2, e3);
            float d = (e0 + e1) + (e2 + e3);
#pragma unroll
            for (int o = 16; o > 0; o >>= 1)
                d += __shfl_xor_sync(FULL, d, o);
            __syncwarp();

            float inv = 1.0f / d;
            int slot = t & (RING - 1);
            rec[slot][lane]      = esc[w][ext0] * inv;
            rec[slot][lane + 32] = esc[w][ext1] * inv;
            if (lane == 0) rec[slot][64] = esc[w][0] * inv;

            __syncwarp();                      // order lanes' stores before flag
            if (lane == 0) strel(&ready[slot], t);
        }
    } else {
        // ---------------- consumer: serial alpha recursion -----------------
        float sk0 = 0.f, sk1 = 0.f;            // skip-allowed per odd state
        if (lane & 1) {
            if (lane >= 3) sk0 = (lab[lane >> 1] != lab[(lane >> 1) - 1]) ? 1.f : 0.f;
            sk1 = (lab[16 + (lane >> 1)] != lab[15 + (lane >> 1)]) ? 1.f : 0.f;
        }

        // virtual alpha_{-1} = delta at s=0 makes t=0 a normal step
        float a0 = (lane == 0) ? 1.f : 0.f;
        float a1 = 0.f;
        float a2 = 0.f;                        // s=64 (uniform across lanes)
        float acc = 0.f;

        for (int tb = 0; tb < T_DIM; tb += 8) {
#pragma unroll
            for (int u = 0; u < 8; ++u) {
                const int t = tb + u, slot = t & (RING - 1);
                while (ldacq(&ready[slot]) < t) { __nanosleep(32); }

                float eg0 = rec[slot][lane];
                float eg1 = rec[slot][lane + 32];
                float eb  = rec[slot][64];

                float u0_1  = __shfl_up_sync(FULL, a0, 1);
                float u0_2  = __shfl_up_sync(FULL, a0, 2);
                float u1_1  = __shfl_up_sync(FULL, a1, 1);
                float u1_2  = __shfl_up_sync(FULL, a1, 2);
                float a0_31 = __shfl_sync(FULL, a0, 31);
                float a0_30 = __shfl_sync(FULL, a0, 30);
                float a1_31 = __shfl_sync(FULL, a1, 31);

                float am1_0 = (lane == 0) ? 0.f : u0_1;
                float am2_0 = (lane <  2) ? 0.f : u0_2;
                float am1_1 = (lane == 0) ? a0_31 : u1_1;
                float am2_1 = (lane == 0) ? a0_30 : ((lane == 1) ? a0_31 : u1_2);

                a2 = (a2 + a1_31) * eb;        // uses pre-update a1_31
                float n0 = (a0 + am1_0 + sk0 * am2_0) * eg0;
                float n1 = (a1 + am1_1 + sk1 * am2_1) * eg1;
                a0 = n0; a1 = n1;
            }
            // rescale every 8 steps (p<=1 so alpha only shrinks; avoid underflow)
            float ps = a0 + a1 + ((lane == 0) ? a2 : 0.f);
#pragma unroll
            for (int o = 16; o > 0; o >>= 1)
                ps += __shfl_xor_sync(FULL, ps, o);
            float r = 1.0f / ps;
            a0 *= r; a1 *= r; a2 *= r;
            acc += __logf(ps);

            __syncwarp();                      // reads done before releasing ring
            if (lane == 0) strel(&cons_t, tb + 8);
        }

        float a1_31 = __shfl_sync(FULL, a1, 31);
        if (lane == 0)
            out[b] = -(__logf(a1_31 + a2) + acc);
    }
}

extern "C" void kernel_launch(void* const* d_in, const int* in_sizes, int n_in,
                              void* d_out, int out_size)
{
    const int B = out_size;
    const int*   y_true;
    const float* y_pred;
    if (in_sizes[0] < in_sizes[1]) {       // labels buffer is the smaller one
        y_true = (const int*)d_in[0];
        y_pred = (const float*)d_in[1];
    } else {
        y_true = (const int*)d_in[1];
        y_pred = (const float*)d_in[0];
    }
    float* outp = (float*)d_out;

    ctc_kernel<<<B, 128>>>(y_true, y_pred, outp, B);
}

// round 5
// speedup vs baseline: 1.0902x; 1.0902x over previous
#include <cuda_runtime.h>
#include <cuda_bf16.h>
#include <cstdint>

// CTC loss, two-pass.
// Pass 1 (throughput): one warp per (b,t); softmax over C=128, store the 33
//   needed normalized probs as bf16 in paired layout:
//   slot 2i = label i, slot 2i+1 = label i+16 (i=0..15), slot 32 = blank.
// Pass 2 (latency): one warp per row; serial alpha recursion, one 4B load per
//   lane per timestep.
#define T_DIM 256
#define C_DIM 128
#define L_DIM 32
#define MAXB  2048
#define NV    34      // per (b,t): 32 labels + blank + pad  (68B, 4B-aligned)
#define P1W   8
#define PF2   8
#define WPB2  4

__device__ __nv_bfloat16 g_probs[(size_t)MAXB * T_DIM * NV];

// ---------------- pass 1: one warp per (b,t) --------------------------------
__global__ __launch_bounds__(P1W * 32)
void ctc_pass1(const int* __restrict__ y_true,
               const float* __restrict__ y_pred, int BT)
{
    __shared__ float esc[P1W][C_DIM];

    const int w    = threadIdx.x >> 5;
    const int lane = threadIdx.x & 31;
    const int wg   = blockIdx.x * P1W + w;
    if (wg >= BT) return;
    const int b = wg >> 8;                 // T_DIM == 256

    // classes this lane will store (paired layout); independent of exp chain
    int cA = 0, cB = 0;                    // lane 16 -> blank/blank (slot 32/33)
    if (lane < 16) {
        cA = __ldg(&y_true[b * L_DIM + lane]);
        cB = __ldg(&y_true[b * L_DIM + lane + 16]);
    }

    const float4* rp = reinterpret_cast<const float4*>(y_pred + (size_t)wg * C_DIM);
    float4 x = rp[lane];

    float e0 = __expf(x.x), e1 = __expf(x.y);
    float e2 = __expf(x.z), e3 = __expf(x.w);
    reinterpret_cast<float4*>(esc[w])[lane] = make_float4(e0, e1, e2, e3);
    float d = (e0 + e1) + (e2 + e3);
#pragma unroll
    for (int o = 16; o > 0; o >>= 1)
        d += __shfl_xor_sync(0xffffffffu, d, o);
    __syncwarp();

    if (lane < 17) {
        float inv = 1.0f / d;
        float pA = esc[w][cA] * inv;
        float pB = esc[w][cB] * inv;
        *reinterpret_cast<__nv_bfloat162*>(&g_probs[(size_t)wg * NV + 2 * lane]) =
            __floats2bfloat162_rn(pA, pB);
    }
}

// ---------------- pass 2: one warp per row ----------------------------------
__global__ __launch_bounds__(WPB2 * 32)
void ctc_pass2(const int* __restrict__ y_true,
               float* __restrict__ out, int B)
{
    const int w    = threadIdx.x >> 5;
    const int lane = threadIdx.x & 31;
    const int b    = blockIdx.x * WPB2 + w;
    if (b >= B) return;
    const unsigned FULL = 0xffffffffu;

    const bool odd = (lane & 1);
    // element offset of this lane's bfloat162: odd -> its label pair, even -> blank
    const int off = odd ? ((lane >> 1) * 2) : 32;

    const int* lab = y_true + (size_t)b * L_DIM;
    float sk0 = 0.f, sk1 = 0.f;
    if (odd) {
        if (lane >= 3) sk0 = (lab[lane >> 1] != lab[(lane >> 1) - 1]) ? 1.f : 0.f;
        sk1 = (lab[16 + (lane >> 1)] != lab[15 + (lane >> 1)]) ? 1.f : 0.f;
    }

    const __nv_bfloat16* pb = g_probs + (size_t)b * T_DIM * NV;

    __nv_bfloat162 ring[PF2];
#pragma unroll
    for (int i = 0; i < PF2; ++i)
        ring[i] = *reinterpret_cast<const __nv_bfloat162*>(&pb[i * NV + off]);

    float a0 = (lane == 0) ? 1.f : 0.f;   // virtual alpha_{-1} = delta(s=0)
    float a1 = 0.f;
    float a2 = 0.f;                        // s = 64 (uniform across lanes)
    float acc = 0.f;

    for (int tb = 0; tb < T_DIM; tb += 8) {
#pragma unroll
        for (int u = 0; u < 8; ++u) {
            const int t  = tb + u;
            const int ri = t & (PF2 - 1);

            float2 pr  = __bfloat1622float2(ring[ri]);
            float eg0  = pr.x;                  // odd: label (l>>1)   | even: blank
            float eg1  = odd ? pr.y : pr.x;     // odd: label 16+(l>>1)| even: blank
            float eb   = __shfl_sync(FULL, pr.x, 0);   // blank prob (lane 0 even)

            if (t + PF2 < T_DIM)
                ring[ri] = *reinterpret_cast<const __nv_bfloat162*>(
                               &pb[(t + PF2) * NV + off]);

            float u0_1  = __shfl_up_sync(FULL, a0, 1);
            float u0_2  = __shfl_up_sync(FULL, a0, 2);
            float u1_1  = __shfl_up_sync(FULL, a1, 1);
            float u1_2  = __shfl_up_sync(FULL, a1, 2);
            float a0_31 = __shfl_sync(FULL, a0, 31);
            float a0_30 = __shfl_sync(FULL, a0, 30);
            float a1_31 = __shfl_sync(FULL, a1, 31);

            float am1_0 = (lane == 0) ? 0.f : u0_1;
            float am2_0 = (lane <  2) ? 0.f : u0_2;
            float am1_1 = (lane == 0) ? a0_31 : u1_1;
            float am2_1 = (lane == 0) ? a0_30 : ((lane == 1) ? a0_31 : u1_2);

            a2 = (a2 + a1_31) * eb;            // uses pre-update a1_31
            float n0 = (a0 + am1_0 + sk0 * am2_0) * eg0;
            float n1 = (a1 + am1_1 + sk1 * am2_1) * eg1;
            a0 = n0; a1 = n1;
        }
        // rescale every 8 steps (p <= 1, alpha shrinks ~ (3/128)^8)
        float ps = a0 + a1 + ((lane == 0) ? a2 : 0.f);
#pragma unroll
        for (int o = 16; o > 0; o >>= 1)
            ps += __shfl_xor_sync(FULL, ps, o);
        float r = 1.0f / ps;
        a0 *= r; a1 *= r; a2 *= r;
        acc += __logf(ps);
    }

    float a1_31 = __shfl_sync(FULL, a1, 31);
    if (lane == 0)
        out[b] = -(__logf(a1_31 + a2) + acc);
}

extern "C" void kernel_launch(void* const* d_in, const int* in_sizes, int n_in,
                              void* d_out, int out_size)
{
    const int B = out_size;
    const int*   y_true;
    const float* y_pred;
    if (in_sizes[0] < in_sizes[1]) {       // labels buffer is the smaller one
        y_true = (const int*)d_in[0];
        y_pred = (const float*)d_in[1];
    } else {
        y_true = (const int*)d_in[1];
        y_pred = (const float*)d_in[0];
    }
    float* outp = (float*)d_out;

    const int BT = B * T_DIM;
    ctc_pass1<<<(BT + P1W - 1) / P1W, P1W * 32>>>(y_true, y_pred, BT);
    ctc_pass2<<<(B + WPB2 - 1) / WPB2, WPB2 * 32>>>(y_true, outp, B);
}

// round 6
// speedup vs baseline: 1.5554x; 1.4267x over previous
#include <cuda_runtime.h>
#include <cuda_bf16.h>
#include <cstdint>

// CTC loss, two-pass.
// Pass 1: one warp per FOUR timesteps (b, t0..t0+3). Softmax over C=128,
//   store normalized probs: labels t-paired ([b][t/2][32] x bfloat162) and
//   blanks ([b][t] bf16).
// Pass 2: one warp per row; lane l owns states 2l (blank) and 2l+1 (label l);
//   one shfl_up feeds both updates. s=64 kept uniform on all lanes.
#define T_DIM 256
#define C_DIM 128
#define L_DIM 32
#define MAXB  2048
#define P1W   8
#define WPB2  4

// label probs, t-paired: entry (b, tp, l) = {p_{2tp}[lab_l], p_{2tp+1}[lab_l]}
__device__ unsigned       g_lab[(size_t)MAXB * (T_DIM / 2) * L_DIM];
__device__ __nv_bfloat16  g_blank[(size_t)MAXB * T_DIM];

// ---------------- pass 1 ----------------------------------------------------
__global__ __launch_bounds__(P1W * 32)
void ctc_pass1(const int* __restrict__ y_true,
               const float* __restrict__ y_pred, int BT4)
{
    __shared__ float esc[P1W][4][C_DIM];

    const int w    = threadIdx.x >> 5;
    const int lane = threadIdx.x & 31;
    const int wg   = blockIdx.x * P1W + w;
    if (wg >= BT4) return;
    const int b  = wg >> 6;                 // 64 groups of 4 timesteps per row
    const int t0 = (wg & 63) * 4;

    const int labl = y_true[b * L_DIM + lane];   // this lane's gather class

    const float4* rp = reinterpret_cast<const float4*>(
        y_pred + ((size_t)b * T_DIM + t0) * C_DIM);

    // 4 independent loads in flight
    float4 x0 = rp[lane];
    float4 x1 = rp[32 + lane];
    float4 x2 = rp[64 + lane];
    float4 x3 = rp[96 + lane];

    float4 xt[4] = {x0, x1, x2, x3};
    float  d[4], ez[4];
#pragma unroll
    for (int i = 0; i < 4; ++i) {
        float e0 = __expf(xt[i].x), e1 = __expf(xt[i].y);
        float e2 = __expf(xt[i].z), e3 = __expf(xt[i].w);
        reinterpret_cast<float4*>(esc[w][i])[lane] = make_float4(e0, e1, e2, e3);
        d[i]  = (e0 + e1) + (e2 + e3);
        ez[i] = e0;                          // lane0's e0 = exp at class 0 (blank)
    }
    // 4 interleaved butterflies (independent chains)
#pragma unroll
    for (int o = 16; o > 0; o >>= 1) {
#pragma unroll
        for (int i = 0; i < 4; ++i)
            d[i] += __shfl_xor_sync(0xffffffffu, d[i], o);
    }
    __syncwarp();

    float inv[4];
#pragma unroll
    for (int i = 0; i < 4; ++i) inv[i] = __fdividef(1.0f, d[i]);

    // gather own label prob for each of the 4 timesteps
    float p[4];
#pragma unroll
    for (int i = 0; i < 4; ++i) p[i] = esc[w][i][labl] * inv[i];

    // paired label stores: (t0,t0+1) and (t0+2,t0+3) -> one 128B line each
    unsigned* gl = g_lab + ((size_t)b * (T_DIM / 2) + (t0 >> 1)) * L_DIM;
    __nv_bfloat162 pr01 = __floats2bfloat162_rn(p[0], p[1]);
    __nv_bfloat162 pr23 = __floats2bfloat162_rn(p[2], p[3]);
    gl[lane]          = *reinterpret_cast<unsigned*>(&pr01);
    gl[L_DIM + lane]  = *reinterpret_cast<unsigned*>(&pr23);

    // blanks: lane0 owns class 0; pack 4 bf16 -> 8B aligned store
    if (lane == 0) {
        __nv_bfloat162 b01 = __floats2bfloat162_rn(ez[0] * inv[0], ez[1] * inv[1]);
        __nv_bfloat162 b23 = __floats2bfloat162_rn(ez[2] * inv[2], ez[3] * inv[3]);
        uint2 pk;
        pk.x = *reinterpret_cast<unsigned*>(&b01);
        pk.y = *reinterpret_cast<unsigned*>(&b23);
        *reinterpret_cast<uint2*>(&g_blank[(size_t)b * T_DIM + t0]) = pk;
    }
}

// ---------------- pass 2 ----------------------------------------------------
__global__ __launch_bounds__(WPB2 * 32)
void ctc_pass2(const int* __restrict__ y_true,
               float* __restrict__ out, int B)
{
    const int w    = threadIdx.x >> 5;
    const int lane = threadIdx.x & 31;
    const int b    = blockIdx.x * WPB2 + w;
    if (b >= B) return;
    const unsigned FULL = 0xffffffffu;

    // lane l: a_e = alpha[2l] (blank), a_o = alpha[2l+1] (label l); a64 uniform
    const int* lab = y_true + (size_t)b * L_DIM;
    const float m0 = (lane == 0) ? 0.f : 1.f;          // mask for alpha[2l-1]
    float sk = 0.f;
    if (lane >= 1) sk = (lab[lane] != lab[lane - 1]) ? 1.f : 0.f;

    const unsigned* gl = g_lab + (size_t)b * (T_DIM / 2) * L_DIM;
    const __nv_bfloat16* gb = g_blank + (size_t)b * T_DIM;

    // label ring: 4 pairs (8 timesteps) ahead; blank block: 8 per load
    unsigned ring[4];
#pragma unroll
    for (int i = 0; i < 4; ++i) ring[i] = gl[i * L_DIM + lane];
    uint4 bcur = *reinterpret_cast<const uint4*>(gb);   // blanks t=0..7

    float a_e = (lane == 0) ? 1.f : 0.f;   // virtual alpha_{-1} = delta(s=0)
    float a_o = 0.f;
    float a64 = 0.f;
    float acc = 0.f;

    for (int tb = 0; tb < T_DIM; tb += 8) {
        // decode this block's 8 blank probs (off the alpha chain)
        float bl[8];
        {
            const __nv_bfloat16* bp = reinterpret_cast<const __nv_bfloat16*>(&bcur);
#pragma unroll
            for (int i = 0; i < 8; ++i) bl[i] = __bfloat162float(bp[i]);
        }
        if (tb + 8 < T_DIM)
            bcur = *reinterpret_cast<const uint4*>(gb + tb + 8);

#pragma unroll
        for (int u = 0; u < 4; ++u) {                   // u = pair within block
            const int tp = (tb >> 1) + u;
            const int ri = tp & 3;
            __nv_bfloat162 prh = *reinterpret_cast<__nv_bfloat162*>(&ring[ri]);
            float2 pr = __bfloat1622float2(prh);        // label probs t, t+1
            if (tp + 4 < (T_DIM / 2))
                ring[ri] = gl[(tp + 4) * L_DIM + lane];

#pragma unroll
            for (int h = 0; h < 2; ++h) {
                float pl = (h == 0) ? pr.x : pr.y;
                float bt = bl[2 * u + h];

                float uo = __shfl_up_sync(FULL, a_o, 1);
                float v  = __shfl_sync(FULL, a_o, 31);
                float um = uo * m0;                      // alpha[2l-1]

                float ae_n = (a_e + um) * bt;
                float ao_n = ((a_o + a_e) + sk * um) * pl;
                a64 = (a64 + v) * bt;
                a_e = ae_n; a_o = ao_n;
            }
        }

        // renormalize every 8 steps
        float ps = a_e + a_o + ((lane == 0) ? a64 : 0.f);
#pragma unroll
        for (int o = 16; o > 0; o >>= 1)
            ps += __shfl_xor_sync(FULL, ps, o);
        float r = __fdividef(1.0f, ps);
        a_e *= r; a_o *= r; a64 *= r;
        acc += __logf(ps);
    }

    float a63 = __shfl_sync(FULL, a_o, 31);
    if (lane == 0)
        out[b] = -(__logf(a63 + a64) + acc);
}

extern "C" void kernel_launch(void* const* d_in, const int* in_sizes, int n_in,
                              void* d_out, int out_size)
{
    const int B = out_size;
    const int*   y_true;
    const float* y_pred;
    if (in_sizes[0] < in_sizes[1]) {       // labels buffer is the smaller one
        y_true = (const int*)d_in[0];
        y_pred = (const float*)d_in[1];
    } else {
        y_true = (const int*)d_in[1];
        y_pred = (const float*)d_in[0];
    }
    float* outp = (float*)d_out;

    const int BT4 = B * (T_DIM / 4);
    ctc_pass1<<<(BT4 + P1W - 1) / P1W, P1W * 32>>>(y_true, y_pred, BT4);
    ctc_pass2<<<(B + WPB2 - 1) / WPB2, WPB2 * 32>>>(y_true, outp, B);
}